// round 8
// baseline (speedup 1.0000x reference)
#include <cuda_runtime.h>
#include <math.h>
#include <stdint.h>

#define B_  8
#define C_  256
#define IC_ 128
#define NQ  4096     // 64*64
#define NKV 1024     // 32*32

typedef unsigned long long u64;

// ---------------- f32x2 packed-FMA helpers (FFMA2 — PTX-only on sm_103a) ----------------
__device__ __forceinline__ u64 pack2(float x, float y) {
    u64 r;
    asm("mov.b64 %0, {%1, %2};" : "=l"(r) : "f"(x), "f"(y));
    return r;
}
__device__ __forceinline__ float2 unpack2(u64 v) {
    float2 f;
    asm("mov.b64 {%0, %1}, %2;" : "=f"(f.x), "=f"(f.y) : "l"(v));
    return f;
}
__device__ __forceinline__ u64 ffma2(u64 a, u64 b, u64 c) {
    u64 d;
    asm("fma.rn.f32x2 %0, %1, %2, %3;" : "=l"(d) : "l"(a), "l"(b), "l"(c));
    return d;
}
__device__ __forceinline__ u64 fmul2(u64 a, u64 b) {
    u64 d;
    asm("mul.rn.f32x2 %0, %1, %2;" : "=l"(d) : "l"(a), "l"(b));
    return d;
}

// ---------------- scratch (no allocs allowed) ----------------
__device__ float s_rgbp[B_*C_*NQ];     // pooled rgb   [b][256][4096]
__device__ float s_evp [B_*C_*NQ];     // pooled event [b][256][4096]
__device__ float s_theta[B_*IC_*NQ];   // [b][128][4096]
__device__ float s_convg[B_*IC_*NQ];   // conv(g) full res
__device__ float s_convphi[B_*IC_*NQ]; // conv(phi) full res
__device__ float s_gx  [B_*NKV*IC_];   // pooled g, transposed [b][kv][128]
__device__ float s_phip[B_*IC_*NKV];   // pooled phi [b][128][1024]
__device__ float s_y   [B_*IC_*NQ];    // attention output [b][128][4096]
__device__ float s_wy  [B_*C_*NQ];     // W conv output [b][256][4096]
__device__ float s_bnsum[C_];
__device__ float s_bnsq [C_];

// ---------------- kernel 1: 2x2 maxpool (128x128 -> 64x64) ----------------
__global__ void pool_kernel(const float* __restrict__ in, float* __restrict__ out, int zero_bn)
{
    int idx = blockIdx.x * 256 + threadIdx.x;         // over B*C*4096
    if (zero_bn && blockIdx.x == 0 && threadIdx.x < C_) {
        s_bnsum[threadIdx.x] = 0.f;
        s_bnsq [threadIdx.x] = 0.f;
    }
    int p = idx & 4095;
    int plane = idx >> 12;                            // b*C + c
    int i = p >> 6, j = p & 63;
    const float2* in2 = (const float2*)in + (size_t)plane * 8192;  // 128*128/2
    float2 a = in2[(2*i)   * 64 + j];
    float2 b = in2[(2*i+1) * 64 + j];
    out[idx] = fmaxf(fmaxf(a.x, a.y), fmaxf(b.x, b.y));
}

// ---------------- kernel 2: conv1x1 GEMM  out[b][o][n] = sum_c w[o][c] x[b][c][n] + bias[o]
// block tile: 64 O x 128 N, K chunk 32.  256 threads, 8Ox(2x n-pair) per thread, FFMA2.
template<bool DO_BN>
__global__ void __launch_bounds__(256) conv_gemm(
    const float* __restrict__ x, const float* __restrict__ w,
    const float* __restrict__ bias, float* __restrict__ out, int C)
{
    __shared__ float a_s[32][68];     // [k][o]
    __shared__ float x_s[32][128];    // [k][n]
    const int t = threadIdx.x;
    const int warp = t >> 5, lane = t & 31;
    const int to = warp * 8;
    const int tn = lane * 4;
    const int n0 = blockIdx.x * 128;
    const int o0 = blockIdx.y * 64;
    const int Ototal = gridDim.y * 64;
    const float* xb = x + (size_t)blockIdx.z * C * NQ + n0;
    const float* wb = w + (size_t)o0 * C;

    u64 acc2[8][2];
#pragma unroll
    for (int i = 0; i < 8; i++) { acc2[i][0] = 0ull; acc2[i][1] = 0ull; }

    for (int k0 = 0; k0 < C; k0 += 32) {
        __syncthreads();
#pragma unroll
        for (int i = 0; i < 8; i++) {            // A tile 64x32
            int ii = t + i * 256;
            int o = ii >> 5, k = ii & 31;
            a_s[k][o] = wb[(size_t)o * C + k0 + k];
        }
#pragma unroll
        for (int i = 0; i < 4; i++) {            // X tile 32x128 (float4)
            int ii = t + i * 256;                // 1024 float4 slots
            int k = ii >> 5, n4 = (ii & 31) * 4;
            *(float4*)&x_s[k][n4] = *(const float4*)&xb[(size_t)(k0 + k) * NQ + n4];
        }
        __syncthreads();
#pragma unroll 2
        for (int k = 0; k < 32; k++) {
            float4 xv = *(float4*)&x_s[k][tn];
            const u64* xp = (const u64*)&xv;         // 2 n-pairs (free reinterpret)
            u64 xlo = xp[0], xhi = xp[1];
            float4 a0 = *(float4*)&a_s[k][to];
            float4 a1 = *(float4*)&a_s[k][to + 4];
            float ar[8] = {a0.x,a0.y,a0.z,a0.w,a1.x,a1.y,a1.z,a1.w};
#pragma unroll
            for (int oi = 0; oi < 8; oi++) {
                u64 ap = pack2(ar[oi], ar[oi]);
                acc2[oi][0] = ffma2(ap, xlo, acc2[oi][0]);
                acc2[oi][1] = ffma2(ap, xhi, acc2[oi][1]);
            }
        }
    }

    float* ob = out + (size_t)blockIdx.z * Ototal * NQ;
#pragma unroll
    for (int oi = 0; oi < 8; oi++) {
        int o = o0 + to + oi;
        float bv = bias[o];
        float2 u0 = unpack2(acc2[oi][0]);
        float2 u1 = unpack2(acc2[oi][1]);
        float4 v;
        v.x = u0.x + bv; v.y = u0.y + bv;
        v.z = u1.x + bv; v.w = u1.y + bv;
        *(float4*)&ob[(size_t)o * NQ + n0 + tn] = v;
        if (DO_BN) {
            float s = v.x + v.y + v.z + v.w;
            float q = v.x*v.x + v.y*v.y + v.z*v.z + v.w*v.w;
#pragma unroll
            for (int off = 16; off; off >>= 1) {
                s += __shfl_xor_sync(0xffffffffu, s, off);
                q += __shfl_xor_sync(0xffffffffu, q, off);
            }
            if (lane == 0) { atomicAdd(&s_bnsum[o], s); atomicAdd(&s_bnsq[o], q); }
        }
    }
}

// ---------------- kernel 3a: pool conv(g) 64x64->32x32 AND transpose to [b][kv][c]
__global__ void pool_g_kernel()
{
    __shared__ float ps[128][33];
    const int t = threadIdx.x;
    const int b = blockIdx.z;
    const int c0 = blockIdx.y * 32;
    const int kv0 = blockIdx.x * 128;
    const int c_off = t >> 7;       // 0..1
    const int p = t & 127;
    const int kv = kv0 + p;
    const int pr = kv >> 5, pc = kv & 31;
    const float2* base = (const float2*)s_convg + (size_t)b * IC_ * 2048;  // 4096 floats/plane
    for (int cc = 0; cc < 32; cc += 2) {
        int c = c0 + cc + c_off;
        const float2* pl = base + (size_t)c * 2048;
        float2 a = pl[(2*pr)   * 32 + pc];
        float2 d = pl[(2*pr+1) * 32 + pc];
        ps[p][cc + c_off] = fmaxf(fmaxf(a.x, a.y), fmaxf(d.x, d.y));
    }
    __syncthreads();
    float* outb = s_gx + (size_t)b * NKV * IC_;
#pragma unroll
    for (int i = 0; i < 16; i++) {
        int ii = t + i * 256;                 // 0..4095
        int pp = ii >> 5, c = ii & 31;
        outb[(size_t)(kv0 + pp) * IC_ + c0 + c] = ps[pp][c];
    }
}

// ---------------- kernel 3b: pool conv(phi) -> [b][c][1024]
__global__ void pool_phi_kernel()
{
    int idx = blockIdx.x * 256 + threadIdx.x;   // B*128*1024
    int kv = idx & 1023;
    int plane = idx >> 10;                      // b*128 + c
    int pr = kv >> 5, pc = kv & 31;
    const float2* pl = (const float2*)s_convphi + (size_t)plane * 2048;
    float2 a = pl[(2*pr)   * 32 + pc];
    float2 d = pl[(2*pr+1) * 32 + pc];
    s_phip[idx] = fmaxf(fmaxf(a.x, a.y), fmaxf(d.x, d.y));
}

// ---------------- kernel 4: fused flash attention (FFMA2 + register softmax) ----------------
// block: 64 queries, one batch.  loop over 8 kv tiles of 128.
#define P_STRIDE 132
#define ATTN_SMEM_FLOATS (128*64 + 128*128 + 64*P_STRIDE)

__global__ void __launch_bounds__(256) attn_kernel()
{
    extern __shared__ float sm[];
    float* th_s = sm;                   // theta [c][q] stride 64  (32 KB)
    float* kv_s = th_s + 128 * 64;      // phi [c][k]128, then g [k][c]128  (64 KB)
    float* p_s  = kv_s + 128 * 128;     // P [q][k] stride 132  (33.8 KB)

    const int t = threadIdx.x;
    const int warp = t >> 5, lane = t & 31;
    const int b = blockIdx.y;
    const int q0 = blockIdx.x * 64;
    const int tq8 = warp * 8;           // this warp owns q rows tq8..tq8+7 (QK and PV)
    const int tk4 = lane * 4;           // k micro (QK)
    const int tc4 = lane * 4;           // c micro (PV)

    const float* theta_b = s_theta + (size_t)b * IC_ * NQ;
    const float* phi_b   = s_phip  + (size_t)b * IC_ * NKV;
    const float* g_b     = s_gx    + (size_t)b * NKV * IC_;

    // load theta tile [c][q]
#pragma unroll
    for (int i = 0; i < 8; i++) {
        int ii = t + i * 256;              // 2048 float4
        int c = ii >> 4, q4 = (ii & 15) * 4;
        *(float4*)&th_s[c * 64 + q4] = *(const float4*)&theta_b[(size_t)c * NQ + q0 + q4];
    }

    float m_run[8], l_run[8];
    u64 y2[8][2];                          // y accumulator: 8 q x 2 c-pairs
#pragma unroll
    for (int i = 0; i < 8; i++) {
        m_run[i] = -3.0e38f; l_run[i] = 0.f;
        y2[i][0] = 0ull; y2[i][1] = 0ull;
    }

    for (int kt = 0; kt < NKV; kt += 128) {
        __syncthreads();                                     // (A) prev PV done; theta visible
        // load phi tile [c][k]
#pragma unroll
        for (int i = 0; i < 16; i++) {
            int ii = t + i * 256;                            // 4096 float4
            int c = ii >> 5, k4 = (ii & 31) * 4;
            *(float4*)&kv_s[c * 128 + k4] = *(const float4*)&phi_b[(size_t)c * NKV + kt + k4];
        }
        __syncthreads();                                     // (B)

        // QK: s2[qp][ki] = pair (S[2qp][k], S[2qp+1][k]); theta pairs free via reinterpret
        u64 s2[4][4];
#pragma unroll
        for (int i = 0; i < 4; i++)
#pragma unroll
            for (int j = 0; j < 4; j++) s2[i][j] = 0ull;
#pragma unroll 2
        for (int c = 0; c < 128; c++) {
            float4 pv = *(float4*)&kv_s[c * 128 + tk4];
            float4 t0 = *(float4*)&th_s[c * 64 + tq8];
            float4 t1 = *(float4*)&th_s[c * 64 + tq8 + 4];
            const u64* tp0 = (const u64*)&t0;
            const u64* tp1 = (const u64*)&t1;
            u64 tq[4] = {tp0[0], tp0[1], tp1[0], tp1[1]};    // q-pairs
            u64 pk0 = pack2(pv.x, pv.x);
            u64 pk1 = pack2(pv.y, pv.y);
            u64 pk2 = pack2(pv.z, pv.z);
            u64 pk3 = pack2(pv.w, pv.w);
#pragma unroll
            for (int qp = 0; qp < 4; qp++) {
                s2[qp][0] = ffma2(tq[qp], pk0, s2[qp][0]);
                s2[qp][1] = ffma2(tq[qp], pk1, s2[qp][1]);
                s2[qp][2] = ffma2(tq[qp], pk2, s2[qp][2]);
                s2[qp][3] = ffma2(tq[qp], pk3, s2[qp][3]);
            }
        }
        // unpack scores: sv[qi][ki]
        float sv[8][4];
#pragma unroll
        for (int qp = 0; qp < 4; qp++)
#pragma unroll
            for (int ki = 0; ki < 4; ki++) {
                float2 u = unpack2(s2[qp][ki]);
                sv[2*qp][ki]   = u.x;
                sv[2*qp+1][ki] = u.y;
            }
        // register softmax: warp owns full k-range for its 8 q rows
#pragma unroll
        for (int qi = 0; qi < 8; qi++) {
            float mt = fmaxf(fmaxf(sv[qi][0], sv[qi][1]), fmaxf(sv[qi][2], sv[qi][3]));
#pragma unroll
            for (int off = 16; off; off >>= 1)
                mt = fmaxf(mt, __shfl_xor_sync(0xffffffffu, mt, off));
            float mn = fmaxf(m_run[qi], mt);
            float sc = __expf(m_run[qi] - mn);
            m_run[qi] = mn;
            float e0 = __expf(sv[qi][0] - mn);
            float e1 = __expf(sv[qi][1] - mn);
            float e2 = __expf(sv[qi][2] - mn);
            float e3 = __expf(sv[qi][3] - mn);
            sv[qi][0] = e0; sv[qi][1] = e1; sv[qi][2] = e2; sv[qi][3] = e3;
            float ts = e0 + e1 + e2 + e3;
#pragma unroll
            for (int off = 16; off; off >>= 1)
                ts += __shfl_xor_sync(0xffffffffu, ts, off);
            l_run[qi] = l_run[qi] * sc + ts;
            u64 scp = pack2(sc, sc);
            y2[qi][0] = fmul2(y2[qi][0], scp);
            y2[qi][1] = fmul2(y2[qi][1], scp);
        }
        __syncthreads();                                     // (C) kv_s(phi) reads done
        // store P [q][k]
#pragma unroll
        for (int qi = 0; qi < 8; qi++) {
            float4 v = make_float4(sv[qi][0], sv[qi][1], sv[qi][2], sv[qi][3]);
            *(float4*)&p_s[(tq8 + qi) * P_STRIDE + tk4] = v;
        }
        // load g tile [k][c] into kv_s
#pragma unroll
        for (int i = 0; i < 16; i++) {
            int ii = t + i * 256;
            int k = ii >> 5, c4 = (ii & 31) * 4;
            *(float4*)&kv_s[k * 128 + c4] = *(const float4*)&g_b[(size_t)(kt + k) * IC_ + c4];
        }
        __syncthreads();                                     // (D) P + g visible

        // PV: y[q][c] += sum_k P[q][k] * g[k][c]; c-pairs free via reinterpret
#pragma unroll 2
        for (int k0 = 0; k0 < 128; k0 += 4) {
            float4 g0 = *(float4*)&kv_s[(k0 + 0) * 128 + tc4];
            float4 g1 = *(float4*)&kv_s[(k0 + 1) * 128 + tc4];
            float4 g2 = *(float4*)&kv_s[(k0 + 2) * 128 + tc4];
            float4 g3 = *(float4*)&kv_s[(k0 + 3) * 128 + tc4];
            const u64* g0p = (const u64*)&g0;
            const u64* g1p = (const u64*)&g1;
            const u64* g2p = (const u64*)&g2;
            const u64* g3p = (const u64*)&g3;
#pragma unroll
            for (int qi = 0; qi < 8; qi++) {
                float4 pq = *(float4*)&p_s[(tq8 + qi) * P_STRIDE + k0];
                u64 pa = pack2(pq.x, pq.x);
                u64 pb = pack2(pq.y, pq.y);
                u64 pc = pack2(pq.z, pq.z);
                u64 pd = pack2(pq.w, pq.w);
                y2[qi][0] = ffma2(pa, g0p[0], y2[qi][0]);
                y2[qi][1] = ffma2(pa, g0p[1], y2[qi][1]);
                y2[qi][0] = ffma2(pb, g1p[0], y2[qi][0]);
                y2[qi][1] = ffma2(pb, g1p[1], y2[qi][1]);
                y2[qi][0] = ffma2(pc, g2p[0], y2[qi][0]);
                y2[qi][1] = ffma2(pc, g2p[1], y2[qi][1]);
                y2[qi][0] = ffma2(pd, g3p[0], y2[qi][0]);
                y2[qi][1] = ffma2(pd, g3p[1], y2[qi][1]);
            }
        }
    }
    __syncthreads();
    // normalize and stage y as [c][q] in kv_s, then coalesced global write
#pragma unroll
    for (int qi = 0; qi < 8; qi++) {
        float inv = 1.0f / l_run[qi];
        float2 u0 = unpack2(y2[qi][0]);
        float2 u1 = unpack2(y2[qi][1]);
        kv_s[(tc4 + 0) * 64 + tq8 + qi] = u0.x * inv;
        kv_s[(tc4 + 1) * 64 + tq8 + qi] = u0.y * inv;
        kv_s[(tc4 + 2) * 64 + tq8 + qi] = u1.x * inv;
        kv_s[(tc4 + 3) * 64 + tq8 + qi] = u1.y * inv;
    }
    __syncthreads();
    float* yb = s_y + (size_t)b * IC_ * NQ;
#pragma unroll
    for (int i = 0; i < 8; i++) {
        int ii = t + i * 256;               // 2048 float4
        int c = ii >> 4, q4 = (ii & 15) * 4;
        *(float4*)&yb[(size_t)c * NQ + q0 + q4] = *(float4*)&kv_s[c * 64 + q4];
    }
}

// ---------------- kernel 6: BN + residual + 2x nearest upsample ----------------
__global__ void final_kernel(const float* __restrict__ gamma, const float* __restrict__ beta,
                             float* __restrict__ out)
{
    const int b = blockIdx.z, c = blockIdx.y;
    const int p = blockIdx.x * 256 + threadIdx.x;    // 0..4095
    const float invN = 1.0f / 32768.0f;              // B * 64 * 64
    float mean = s_bnsum[c] * invN;
    float var  = s_bnsq[c] * invN - mean * mean;
    float rs = rsqrtf(var + 1e-5f);
    float gm = gamma[c] * rs;
    float bt = beta[c] - mean * gm;
    int i = p >> 6, j = p & 63;
    size_t off = ((size_t)b * C_ + c) * NQ + p;
    float v = s_wy[off] * gm + bt + s_rgbp[off];
    float2 vv = make_float2(v, v);
    float2* o2 = (float2*)out + ((size_t)b * C_ + c) * 8192;   // 128*128/2 per plane
    o2[(2*i)   * 64 + j] = vv;
    o2[(2*i+1) * 64 + j] = vv;
}

// ---------------- launch ----------------
extern "C" void kernel_launch(void* const* d_in, const int* in_sizes, int n_in,
                              void* d_out, int out_size)
{
    const float* rgb     = (const float*)d_in[0];
    const float* event_  = (const float*)d_in[1];
    const float* g_w     = (const float*)d_in[2];
    const float* g_b     = (const float*)d_in[3];
    const float* theta_w = (const float*)d_in[4];
    const float* theta_b = (const float*)d_in[5];
    const float* phi_w   = (const float*)d_in[6];
    const float* phi_b   = (const float*)d_in[7];
    const float* W_w     = (const float*)d_in[8];
    const float* W_b     = (const float*)d_in[9];
    const float* gamma   = (const float*)d_in[10];
    const float* beta    = (const float*)d_in[11];
    float* out = (float*)d_out;

    float *p_rgbp, *p_evp, *p_theta, *p_convg, *p_convphi, *p_y, *p_wy;
    cudaGetSymbolAddress((void**)&p_rgbp,    s_rgbp);
    cudaGetSymbolAddress((void**)&p_evp,     s_evp);
    cudaGetSymbolAddress((void**)&p_theta,   s_theta);
    cudaGetSymbolAddress((void**)&p_convg,   s_convg);
    cudaGetSymbolAddress((void**)&p_convphi, s_convphi);
    cudaGetSymbolAddress((void**)&p_y,       s_y);
    cudaGetSymbolAddress((void**)&p_wy,      s_wy);

    const size_t attn_smem = ATTN_SMEM_FLOATS * sizeof(float);
    cudaFuncSetAttribute(attn_kernel, cudaFuncAttributeMaxDynamicSharedMemorySize, (int)attn_smem);

    // 1) maxpool both modalities (first launch also zeroes BN accumulators)
    pool_kernel<<<32768, 256>>>(rgb, p_rgbp, 1);
    pool_kernel<<<32768, 256>>>(event_, p_evp, 0);

    // 2) projections (conv1x1 GEMMs)
    conv_gemm<false><<<dim3(32, 2, B_), 256>>>(p_rgbp, theta_w, theta_b, p_theta,   C_);
    conv_gemm<false><<<dim3(32, 2, B_), 256>>>(p_evp,  g_w,     g_b,     p_convg,   C_);
    conv_gemm<false><<<dim3(32, 2, B_), 256>>>(p_evp,  phi_w,   phi_b,   p_convphi, C_);

    // 3) sub-sample pools (g transposed for PV layout)
    pool_g_kernel<<<dim3(8, 4, B_), 256>>>();
    pool_phi_kernel<<<4096, 256>>>();

    // 4) fused attention (QK^T -> softmax -> PV)
    attn_kernel<<<dim3(64, B_), 256, attn_smem>>>();

    // 5) output conv + fused BN statistics
    conv_gemm<true><<<dim3(32, 4, B_), 256>>>(p_y, W_w, W_b, p_wy, IC_);

    // 6) BN normalize + residual + 2x upsample
    final_kernel<<<dim3(16, C_, B_), 256>>>(gamma, beta, out);
}

// round 9
// speedup vs baseline: 1.0432x; 1.0432x over previous
#include <cuda_runtime.h>
#include <math.h>
#include <stdint.h>

#define B_  8
#define C_  256
#define IC_ 128
#define NQ  4096     // 64*64
#define NKV 1024     // 32*32

typedef unsigned long long u64;

// ---------------- f32x2 packed-FMA helpers (FFMA2 — PTX-only on sm_103a) ----------------
__device__ __forceinline__ u64 pack2(float x, float y) {
    u64 r;
    asm("mov.b64 %0, {%1, %2};" : "=l"(r) : "f"(x), "f"(y));
    return r;
}
__device__ __forceinline__ float2 unpack2(u64 v) {
    float2 f;
    asm("mov.b64 {%0, %1}, %2;" : "=f"(f.x), "=f"(f.y) : "l"(v));
    return f;
}
__device__ __forceinline__ u64 ffma2(u64 a, u64 b, u64 c) {
    u64 d;
    asm("fma.rn.f32x2 %0, %1, %2, %3;" : "=l"(d) : "l"(a), "l"(b), "l"(c));
    return d;
}
__device__ __forceinline__ u64 fmul2(u64 a, u64 b) {
    u64 d;
    asm("mul.rn.f32x2 %0, %1, %2;" : "=l"(d) : "l"(a), "l"(b));
    return d;
}

// ---------------- scratch (no allocs allowed) ----------------
__device__ float s_rgbp[B_*C_*NQ];     // pooled rgb   [b][256][4096]
__device__ float s_evp [B_*C_*NQ];     // pooled event [b][256][4096]
__device__ float s_theta[B_*IC_*NQ];   // [b][128][4096]
__device__ float s_convg[B_*IC_*NQ];   // conv(g) full res
__device__ float s_convphi[B_*IC_*NQ]; // conv(phi) full res
__device__ float s_gx  [B_*NKV*IC_];   // pooled g, transposed [b][kv][128]
__device__ float s_phip[B_*IC_*NKV];   // pooled phi [b][128][1024]
__device__ float s_y   [B_*IC_*NQ];    // attention output [b][128][4096]
__device__ float s_wy  [B_*C_*NQ];     // W conv output [b][256][4096]
__device__ float s_bnsum[C_];
__device__ float s_bnsq [C_];

// ---------------- kernel 1: 2x2 maxpool (128x128 -> 64x64) ----------------
__global__ void pool_kernel(const float* __restrict__ in, float* __restrict__ out, int zero_bn)
{
    int idx = blockIdx.x * 256 + threadIdx.x;         // over B*C*4096
    if (zero_bn && blockIdx.x == 0 && threadIdx.x < C_) {
        s_bnsum[threadIdx.x] = 0.f;
        s_bnsq [threadIdx.x] = 0.f;
    }
    int p = idx & 4095;
    int plane = idx >> 12;                            // b*C + c
    int i = p >> 6, j = p & 63;
    const float2* in2 = (const float2*)in + (size_t)plane * 8192;  // 128*128/2
    float2 a = in2[(2*i)   * 64 + j];
    float2 b = in2[(2*i+1) * 64 + j];
    out[idx] = fmaxf(fmaxf(a.x, a.y), fmaxf(b.x, b.y));
}

// ---------------- kernel 2: conv1x1 GEMM  out[b][o][n] = sum_c w[o][c] x[b][c][n] + bias[o]
// block tile: 64 O x 128 N, K chunk 32.  256 threads, 8Ox(2x n-pair) per thread, FFMA2.
template<bool DO_BN>
__global__ void __launch_bounds__(256) conv_gemm(
    const float* __restrict__ x, const float* __restrict__ w,
    const float* __restrict__ bias, float* __restrict__ out, int C)
{
    __shared__ float a_s[32][68];     // [k][o]
    __shared__ float x_s[32][128];    // [k][n]
    const int t = threadIdx.x;
    const int warp = t >> 5, lane = t & 31;
    const int to = warp * 8;
    const int tn = lane * 4;
    const int n0 = blockIdx.x * 128;
    const int o0 = blockIdx.y * 64;
    const int Ototal = gridDim.y * 64;
    const float* xb = x + (size_t)blockIdx.z * C * NQ + n0;
    const float* wb = w + (size_t)o0 * C;

    u64 acc2[8][2];
#pragma unroll
    for (int i = 0; i < 8; i++) { acc2[i][0] = 0ull; acc2[i][1] = 0ull; }

    for (int k0 = 0; k0 < C; k0 += 32) {
        __syncthreads();
#pragma unroll
        for (int i = 0; i < 8; i++) {            // A tile 64x32
            int ii = t + i * 256;
            int o = ii >> 5, k = ii & 31;
            a_s[k][o] = wb[(size_t)o * C + k0 + k];
        }
#pragma unroll
        for (int i = 0; i < 4; i++) {            // X tile 32x128 (float4)
            int ii = t + i * 256;                // 1024 float4 slots
            int k = ii >> 5, n4 = (ii & 31) * 4;
            *(float4*)&x_s[k][n4] = *(const float4*)&xb[(size_t)(k0 + k) * NQ + n4];
        }
        __syncthreads();
#pragma unroll 2
        for (int k = 0; k < 32; k++) {
            float4 xv = *(float4*)&x_s[k][tn];
            const u64* xp = (const u64*)&xv;         // 2 n-pairs (free reinterpret)
            u64 xlo = xp[0], xhi = xp[1];
            float4 a0 = *(float4*)&a_s[k][to];
            float4 a1 = *(float4*)&a_s[k][to + 4];
            float ar[8] = {a0.x,a0.y,a0.z,a0.w,a1.x,a1.y,a1.z,a1.w};
#pragma unroll
            for (int oi = 0; oi < 8; oi++) {
                u64 ap = pack2(ar[oi], ar[oi]);
                acc2[oi][0] = ffma2(ap, xlo, acc2[oi][0]);
                acc2[oi][1] = ffma2(ap, xhi, acc2[oi][1]);
            }
        }
    }

    float* ob = out + (size_t)blockIdx.z * Ototal * NQ;
#pragma unroll
    for (int oi = 0; oi < 8; oi++) {
        int o = o0 + to + oi;
        float bv = bias[o];
        float2 u0 = unpack2(acc2[oi][0]);
        float2 u1 = unpack2(acc2[oi][1]);
        float4 v;
        v.x = u0.x + bv; v.y = u0.y + bv;
        v.z = u1.x + bv; v.w = u1.y + bv;
        *(float4*)&ob[(size_t)o * NQ + n0 + tn] = v;
        if (DO_BN) {
            float s = v.x + v.y + v.z + v.w;
            float q = v.x*v.x + v.y*v.y + v.z*v.z + v.w*v.w;
#pragma unroll
            for (int off = 16; off; off >>= 1) {
                s += __shfl_xor_sync(0xffffffffu, s, off);
                q += __shfl_xor_sync(0xffffffffu, q, off);
            }
            if (lane == 0) { atomicAdd(&s_bnsum[o], s); atomicAdd(&s_bnsq[o], q); }
        }
    }
}

// ---------------- kernel 3a: pool conv(g) 64x64->32x32 AND transpose to [b][kv][c]
__global__ void pool_g_kernel()
{
    __shared__ float ps[128][33];
    const int t = threadIdx.x;
    const int b = blockIdx.z;
    const int c0 = blockIdx.y * 32;
    const int kv0 = blockIdx.x * 128;
    const int c_off = t >> 7;       // 0..1
    const int p = t & 127;
    const int kv = kv0 + p;
    const int pr = kv >> 5, pc = kv & 31;
    const float2* base = (const float2*)s_convg + (size_t)b * IC_ * 2048;  // 4096 floats/plane
    for (int cc = 0; cc < 32; cc += 2) {
        int c = c0 + cc + c_off;
        const float2* pl = base + (size_t)c * 2048;
        float2 a = pl[(2*pr)   * 32 + pc];
        float2 d = pl[(2*pr+1) * 32 + pc];
        ps[p][cc + c_off] = fmaxf(fmaxf(a.x, a.y), fmaxf(d.x, d.y));
    }
    __syncthreads();
    float* outb = s_gx + (size_t)b * NKV * IC_;
#pragma unroll
    for (int i = 0; i < 16; i++) {
        int ii = t + i * 256;                 // 0..4095
        int pp = ii >> 5, c = ii & 31;
        outb[(size_t)(kv0 + pp) * IC_ + c0 + c] = ps[pp][c];
    }
}

// ---------------- kernel 3b: pool conv(phi) -> [b][c][1024]
__global__ void pool_phi_kernel()
{
    int idx = blockIdx.x * 256 + threadIdx.x;   // B*128*1024
    int kv = idx & 1023;
    int plane = idx >> 10;                      // b*128 + c
    int pr = kv >> 5, pc = kv & 31;
    const float2* pl = (const float2*)s_convphi + (size_t)plane * 2048;
    float2 a = pl[(2*pr)   * 32 + pc];
    float2 d = pl[(2*pr+1) * 32 + pc];
    s_phip[idx] = fmaxf(fmaxf(a.x, a.y), fmaxf(d.x, d.y));
}

// ---------------- kernel 4: fused flash attention (FFMA2 + register softmax) ----------------
// block: 64 queries, one batch.  loop over 8 kv tiles of 128.
#define P_STRIDE 132
#define ATTN_SMEM_FLOATS (128*64 + 128*128 + 64*P_STRIDE)

__global__ void __launch_bounds__(256) attn_kernel()
{
    extern __shared__ float sm[];
    float* th_s = sm;                   // theta [c][q] stride 64  (32 KB)
    float* kv_s = th_s + 128 * 64;      // phi [c][k]128, then g [k][c]128  (64 KB)
    float* p_s  = kv_s + 128 * 128;     // P [q][k] stride 132  (33.8 KB)

    const int t = threadIdx.x;
    const int warp = t >> 5, lane = t & 31;
    const int b = blockIdx.y;
    const int q0 = blockIdx.x * 64;
    const int tq8 = warp * 8;           // this warp owns q rows tq8..tq8+7 (QK and PV)
    const int tk4 = lane * 4;           // k micro (QK)
    const int tc4 = lane * 4;           // c micro (PV)

    const float* theta_b = s_theta + (size_t)b * IC_ * NQ;
    const float* phi_b   = s_phip  + (size_t)b * IC_ * NKV;
    const float* g_b     = s_gx    + (size_t)b * NKV * IC_;

    // load theta tile [c][q]
#pragma unroll
    for (int i = 0; i < 8; i++) {
        int ii = t + i * 256;              // 2048 float4
        int c = ii >> 4, q4 = (ii & 15) * 4;
        *(float4*)&th_s[c * 64 + q4] = *(const float4*)&theta_b[(size_t)c * NQ + q0 + q4];
    }

    float m_run[8], l_run[8];
    u64 y2[8][2];                          // y accumulator: 8 q x 2 c-pairs
#pragma unroll
    for (int i = 0; i < 8; i++) {
        m_run[i] = -3.0e38f; l_run[i] = 0.f;
        y2[i][0] = 0ull; y2[i][1] = 0ull;
    }

    for (int kt = 0; kt < NKV; kt += 128) {
        __syncthreads();                                     // (A) prev PV done; theta visible
        // load phi tile [c][k]
#pragma unroll
        for (int i = 0; i < 16; i++) {
            int ii = t + i * 256;                            // 4096 float4
            int c = ii >> 5, k4 = (ii & 31) * 4;
            *(float4*)&kv_s[c * 128 + k4] = *(const float4*)&phi_b[(size_t)c * NKV + kt + k4];
        }
        __syncthreads();                                     // (B)

        // QK: s2[qp][ki] = pair (S[2qp][k], S[2qp+1][k]); theta pairs free via reinterpret
        u64 s2[4][4];
#pragma unroll
        for (int i = 0; i < 4; i++)
#pragma unroll
            for (int j = 0; j < 4; j++) s2[i][j] = 0ull;
#pragma unroll 2
        for (int c = 0; c < 128; c++) {
            float4 pv = *(float4*)&kv_s[c * 128 + tk4];
            float4 t0 = *(float4*)&th_s[c * 64 + tq8];
            float4 t1 = *(float4*)&th_s[c * 64 + tq8 + 4];
            const u64* tp0 = (const u64*)&t0;
            const u64* tp1 = (const u64*)&t1;
            u64 tq[4] = {tp0[0], tp0[1], tp1[0], tp1[1]};    // q-pairs
            u64 pk0 = pack2(pv.x, pv.x);
            u64 pk1 = pack2(pv.y, pv.y);
            u64 pk2 = pack2(pv.z, pv.z);
            u64 pk3 = pack2(pv.w, pv.w);
#pragma unroll
            for (int qp = 0; qp < 4; qp++) {
                s2[qp][0] = ffma2(tq[qp], pk0, s2[qp][0]);
                s2[qp][1] = ffma2(tq[qp], pk1, s2[qp][1]);
                s2[qp][2] = ffma2(tq[qp], pk2, s2[qp][2]);
                s2[qp][3] = ffma2(tq[qp], pk3, s2[qp][3]);
            }
        }
        // unpack scores: sv[qi][ki]
        float sv[8][4];
#pragma unroll
        for (int qp = 0; qp < 4; qp++)
#pragma unroll
            for (int ki = 0; ki < 4; ki++) {
                float2 u = unpack2(s2[qp][ki]);
                sv[2*qp][ki]   = u.x;
                sv[2*qp+1][ki] = u.y;
            }
        // register softmax: warp owns full k-range for its 8 q rows
#pragma unroll
        for (int qi = 0; qi < 8; qi++) {
            float mt = fmaxf(fmaxf(sv[qi][0], sv[qi][1]), fmaxf(sv[qi][2], sv[qi][3]));
#pragma unroll
            for (int off = 16; off; off >>= 1)
                mt = fmaxf(mt, __shfl_xor_sync(0xffffffffu, mt, off));
            float mn = fmaxf(m_run[qi], mt);
            float sc = __expf(m_run[qi] - mn);
            m_run[qi] = mn;
            float e0 = __expf(sv[qi][0] - mn);
            float e1 = __expf(sv[qi][1] - mn);
            float e2 = __expf(sv[qi][2] - mn);
            float e3 = __expf(sv[qi][3] - mn);
            sv[qi][0] = e0; sv[qi][1] = e1; sv[qi][2] = e2; sv[qi][3] = e3;
            float ts = e0 + e1 + e2 + e3;
#pragma unroll
            for (int off = 16; off; off >>= 1)
                ts += __shfl_xor_sync(0xffffffffu, ts, off);
            l_run[qi] = l_run[qi] * sc + ts;
            u64 scp = pack2(sc, sc);
            y2[qi][0] = fmul2(y2[qi][0], scp);
            y2[qi][1] = fmul2(y2[qi][1], scp);
        }
        __syncthreads();                                     // (C) kv_s(phi) reads done
        // store P [q][k]
#pragma unroll
        for (int qi = 0; qi < 8; qi++) {
            float4 v = make_float4(sv[qi][0], sv[qi][1], sv[qi][2], sv[qi][3]);
            *(float4*)&p_s[(tq8 + qi) * P_STRIDE + tk4] = v;
        }
        // load g tile [k][c] into kv_s
#pragma unroll
        for (int i = 0; i < 16; i++) {
            int ii = t + i * 256;
            int k = ii >> 5, c4 = (ii & 31) * 4;
            *(float4*)&kv_s[k * 128 + c4] = *(const float4*)&g_b[(size_t)(kt + k) * IC_ + c4];
        }
        __syncthreads();                                     // (D) P + g visible

        // PV: y[q][c] += sum_k P[q][k] * g[k][c]; c-pairs free via reinterpret
#pragma unroll 2
        for (int k0 = 0; k0 < 128; k0 += 4) {
            float4 g0 = *(float4*)&kv_s[(k0 + 0) * 128 + tc4];
            float4 g1 = *(float4*)&kv_s[(k0 + 1) * 128 + tc4];
            float4 g2 = *(float4*)&kv_s[(k0 + 2) * 128 + tc4];
            float4 g3 = *(float4*)&kv_s[(k0 + 3) * 128 + tc4];
            const u64* g0p = (const u64*)&g0;
            const u64* g1p = (const u64*)&g1;
            const u64* g2p = (const u64*)&g2;
            const u64* g3p = (const u64*)&g3;
#pragma unroll
            for (int qi = 0; qi < 8; qi++) {
                float4 pq = *(float4*)&p_s[(tq8 + qi) * P_STRIDE + k0];
                u64 pa = pack2(pq.x, pq.x);
                u64 pb = pack2(pq.y, pq.y);
                u64 pc = pack2(pq.z, pq.z);
                u64 pd = pack2(pq.w, pq.w);
                y2[qi][0] = ffma2(pa, g0p[0], y2[qi][0]);
                y2[qi][1] = ffma2(pa, g0p[1], y2[qi][1]);
                y2[qi][0] = ffma2(pb, g1p[0], y2[qi][0]);
                y2[qi][1] = ffma2(pb, g1p[1], y2[qi][1]);
                y2[qi][0] = ffma2(pc, g2p[0], y2[qi][0]);
                y2[qi][1] = ffma2(pc, g2p[1], y2[qi][1]);
                y2[qi][0] = ffma2(pd, g3p[0], y2[qi][0]);
                y2[qi][1] = ffma2(pd, g3p[1], y2[qi][1]);
            }
        }
    }
    __syncthreads();
    // normalize and stage y as [c][q] in kv_s, then coalesced global write
#pragma unroll
    for (int qi = 0; qi < 8; qi++) {
        float inv = 1.0f / l_run[qi];
        float2 u0 = unpack2(y2[qi][0]);
        float2 u1 = unpack2(y2[qi][1]);
        kv_s[(tc4 + 0) * 64 + tq8 + qi] = u0.x * inv;
        kv_s[(tc4 + 1) * 64 + tq8 + qi] = u0.y * inv;
        kv_s[(tc4 + 2) * 64 + tq8 + qi] = u1.x * inv;
        kv_s[(tc4 + 3) * 64 + tq8 + qi] = u1.y * inv;
    }
    __syncthreads();
    float* yb = s_y + (size_t)b * IC_ * NQ;
#pragma unroll
    for (int i = 0; i < 8; i++) {
        int ii = t + i * 256;               // 2048 float4
        int c = ii >> 4, q4 = (ii & 15) * 4;
        *(float4*)&yb[(size_t)c * NQ + q0 + q4] = *(float4*)&kv_s[c * 64 + q4];
    }
}

// ---------------- kernel 6: BN + residual + 2x nearest upsample ----------------
__global__ void final_kernel(const float* __restrict__ gamma, const float* __restrict__ beta,
                             float* __restrict__ out)
{
    const int b = blockIdx.z, c = blockIdx.y;
    const int p = blockIdx.x * 256 + threadIdx.x;    // 0..4095
    const float invN = 1.0f / 32768.0f;              // B * 64 * 64
    float mean = s_bnsum[c] * invN;
    float var  = s_bnsq[c] * invN - mean * mean;
    float rs = rsqrtf(var + 1e-5f);
    float gm = gamma[c] * rs;
    float bt = beta[c] - mean * gm;
    int i = p >> 6, j = p & 63;
    size_t off = ((size_t)b * C_ + c) * NQ + p;
    float v = s_wy[off] * gm + bt + s_rgbp[off];
    float2 vv = make_float2(v, v);
    float2* o2 = (float2*)out + ((size_t)b * C_ + c) * 8192;   // 128*128/2 per plane
    o2[(2*i)   * 64 + j] = vv;
    o2[(2*i+1) * 64 + j] = vv;
}

// ---------------- launch ----------------
extern "C" void kernel_launch(void* const* d_in, const int* in_sizes, int n_in,
                              void* d_out, int out_size)
{
    const float* rgb     = (const float*)d_in[0];
    const float* event_  = (const float*)d_in[1];
    const float* g_w     = (const float*)d_in[2];
    const float* g_b     = (const float*)d_in[3];
    const float* theta_w = (const float*)d_in[4];
    const float* theta_b = (const float*)d_in[5];
    const float* phi_w   = (const float*)d_in[6];
    const float* phi_b   = (const float*)d_in[7];
    const float* W_w     = (const float*)d_in[8];
    const float* W_b     = (const float*)d_in[9];
    const float* gamma   = (const float*)d_in[10];
    const float* beta    = (const float*)d_in[11];
    float* out = (float*)d_out;

    float *p_rgbp, *p_evp, *p_theta, *p_convg, *p_convphi, *p_y, *p_wy;
    cudaGetSymbolAddress((void**)&p_rgbp,    s_rgbp);
    cudaGetSymbolAddress((void**)&p_evp,     s_evp);
    cudaGetSymbolAddress((void**)&p_theta,   s_theta);
    cudaGetSymbolAddress((void**)&p_convg,   s_convg);
    cudaGetSymbolAddress((void**)&p_convphi, s_convphi);
    cudaGetSymbolAddress((void**)&p_y,       s_y);
    cudaGetSymbolAddress((void**)&p_wy,      s_wy);

    const size_t attn_smem = ATTN_SMEM_FLOATS * sizeof(float);
    cudaFuncSetAttribute(attn_kernel, cudaFuncAttributeMaxDynamicSharedMemorySize, (int)attn_smem);

    // 1) maxpool both modalities (first launch also zeroes BN accumulators)
    pool_kernel<<<32768, 256>>>(rgb, p_rgbp, 1);
    pool_kernel<<<32768, 256>>>(event_, p_evp, 0);

    // 2) projections (conv1x1 GEMMs)
    conv_gemm<false><<<dim3(32, 2, B_), 256>>>(p_rgbp, theta_w, theta_b, p_theta,   C_);
    conv_gemm<false><<<dim3(32, 2, B_), 256>>>(p_evp,  g_w,     g_b,     p_convg,   C_);
    conv_gemm<false><<<dim3(32, 2, B_), 256>>>(p_evp,  phi_w,   phi_b,   p_convphi, C_);

    // 3) sub-sample pools (g transposed for PV layout)
    pool_g_kernel<<<dim3(8, 4, B_), 256>>>();
    pool_phi_kernel<<<4096, 256>>>();

    // 4) fused attention (QK^T -> softmax -> PV)
    attn_kernel<<<dim3(64, B_), 256, attn_smem>>>();

    // 5) output conv + fused BN statistics
    conv_gemm<true><<<dim3(32, 4, B_), 256>>>(p_y, W_w, W_b, p_wy, IC_);

    // 6) BN normalize + residual + 2x upsample
    final_kernel<<<dim3(16, C_, B_), 256>>>(gamma, beta, out);
}